// round 10
// baseline (speedup 1.0000x reference)
#include <cuda_runtime.h>
#include <cuda_bf16.h>

// Output[b,s,:] == mean(knowledge, axis=0) for every (b,s):
// top_k with max_chunks == K selects a permutation of ALL knowledge rows,
// so mean(take(knowledge, top_k), axis=1) == mean(knowledge, axis=0).
//
// R7-R9: totals pinned at 6.62-6.66us across load-counts 16/4/2 and grids
// 128/256 -> warm kernel sits under a fixed launch+ramp cost; the load
// phase is no longer binding. This round minimizes the remaining warm
// critical path: ONE barrier total (each thread privately sums the 16
// smem partials after the single sync), branch-free 8xSTG.128 store tail.
// Shape: 128 CTAs = 4 col-blocks x 32 row-blocks, 512 threads.

#define E_DIM 512
#define K_ROWS 64
#define THREADS 512
#define COLS4 (E_DIM / 4)       // 128 float4 per full row
#define NCB 4                   // column blocks
#define CB4 (COLS4 / NCB)       // 32 float4 columns per block
#define ROWS_PER_CTA 128        // 32 row-blocks cover 4096 rows
#define GROUPS 16               // 512 threads / 32 columns

__global__ void __launch_bounds__(THREADS)
fused_mean_broadcast(const float4* __restrict__ knowledge4,
                     float4* __restrict__ out) {
    __shared__ float4 part[GROUPS * CB4];   // 16 partials x 32 cols, 8KB

    int t = threadIdx.x;
    int c = t & (CB4 - 1);      // column within block: 0..31
    int g = t >> 5;             // group 0..15: sums rows [4g, 4g+4)

    int cb = blockIdx.x & (NCB - 1);   // column block 0..3
    int rb = blockIdx.x >> 2;          // row block 0..31
    int col = cb * CB4 + c;            // global float4 column

    // 4 independent front-batched loads per thread (coalesced).
    float4 s = make_float4(0.f, 0.f, 0.f, 0.f);
#pragma unroll
    for (int k = 0; k < 4; ++k) {
        float4 a = knowledge4[(g * 4 + k) * COLS4 + col];
        s.x += a.x; s.y += a.y; s.z += a.z; s.w += a.w;
    }
    part[g * CB4 + c] = s;
    __syncthreads();            // the ONLY barrier

    // Every thread privately sums the 16 partials of its column.
    // 16 LDS.128, conflict-free (consecutive lanes -> consecutive banks).
    float4 m = make_float4(0.f, 0.f, 0.f, 0.f);
#pragma unroll
    for (int k = 0; k < GROUPS; ++k) {
        float4 p = part[k * CB4 + c];
        m.x += p.x; m.y += p.y; m.z += p.z; m.w += p.w;
    }
    const float inv = 1.0f / (float)K_ROWS;
    m.x *= inv; m.y *= inv; m.z *= inv; m.w *= inv;

    // CTA writes rows [rb*128, rb*128+128) of its 32-float4 column slice.
    // Group g writes 8 rows; warp store = 32 consecutive float4 (coalesced).
    // Branch-free: grid tiles 4096 rows exactly.
    int r0 = rb * ROWS_PER_CTA + g * (ROWS_PER_CTA / GROUPS);
    size_t base = (size_t)r0 * COLS4 + col;
#pragma unroll
    for (int r = 0; r < ROWS_PER_CTA / GROUPS; ++r) {
        out[base + (size_t)r * COLS4] = m;
    }
}

extern "C" void kernel_launch(void* const* d_in, const int* in_sizes, int n_in,
                              void* d_out, int out_size) {
    // d_in[0]: query_embedding [4,1024,512] f32 (unused — output is query-independent)
    // d_in[1]: knowledge [64,512] f32
    const float* knowledge = (const float*)d_in[1];
    float* out = (float*)d_out;

    int rows = out_size / E_DIM;                                 // 4096
    int blocks = NCB * (rows / ROWS_PER_CTA);                    // 128

    fused_mean_broadcast<<<blocks, THREADS>>>(
        reinterpret_cast<const float4*>(knowledge),
        reinterpret_cast<float4*>(out));
}